// round 12
// baseline (speedup 1.0000x reference)
#include <cuda_runtime.h>
#include <math.h>
#include <stdint.h>

// LongcatFlashTopkRouter: T=16384, D=4096, E=256
#define TOP_K 8
#define ROUTED_SCALE 1.5f

#if defined(__CUDA_ARCH__) && \
    (defined(__CUDA_ARCH_FEAT_SM103_ALL) || defined(__CUDA_ARCH_FEAT_SM100_ALL) || \
     defined(__CUDA_ARCH_FEAT_SM101_ALL))
#define HAS_TC 1
#else
#define HAS_TC 0
#endif

// ---------------------------------------------------------------------------
// GEMM via bf16x3 on tcgen05 cta_group::2 (2-CTA MMA, M=256 per pair).
// Cluster (2,1,1); CTA holds its 128 token rows of A + its 64-expert half of
// each N=128 dispatch of B (cg2 B-split contract). W pre-split to bf16 planes.
// ---------------------------------------------------------------------------
#define BM 128
#define BKF 32
#define NSTAGE 4
#define A_HI_OFF 0
#define A_LO_OFF 8192
#define B_HI_OFF 16384
#define B_LO_OFF 24576
#define STAGE_BYTES 32768
#define DYN_SMEM (NSTAGE * STAGE_BYTES + 1024)

// idesc cg2 bf16: F32(1)<<4 | BF16(1)<<7 | BF16(1)<<10 | (N=128/8)<<17 | (M=256/16)<<24
#define IDESC_CG2 0x10200490u
#define TMEM_NCOLS 512
// accumulators: D(h, ks) at col h*128 + ks*256 (each CTA holds its 128 lanes)

// W split into bf16 hi/lo planes, once per launch (2MB each).
__device__ __align__(1024) static uint32_t g_w_hi[524288];
__device__ __align__(1024) static uint32_t g_w_lo[524288];

__device__ __forceinline__ uint32_t pack_bf16x2(float hi, float lo) {
    uint32_t d;
    asm("cvt.rn.bf16x2.f32 %0, %1, %2;" : "=r"(d) : "f"(hi), "f"(lo));
    return d;
}

__device__ __forceinline__ uint32_t smem_u32(const void* p) {
    uint32_t a;
    asm("{ .reg .u64 t; cvta.to.shared.u64 t, %1; cvt.u32.u64 %0, t; }" : "=r"(a) : "l"(p));
    return a;
}

// ------------------------- prep: split W fp32 -> bf16 hi/lo ------------------
__global__ __launch_bounds__(512)
void split_w_kernel(const float4* __restrict__ W4, int n4) {
    int i = blockIdx.x * 512 + threadIdx.x;
    if (i >= n4) return;
    float4 f = W4[i];
    uint32_t h0 = pack_bf16x2(f.y, f.x);
    uint32_t h1 = pack_bf16x2(f.w, f.z);
    float a0 = __uint_as_float(h0 << 16);
    float a1 = __uint_as_float(h0 & 0xFFFF0000u);
    float a2 = __uint_as_float(h1 << 16);
    float a3 = __uint_as_float(h1 & 0xFFFF0000u);
    uint32_t l0 = pack_bf16x2(f.y - a1, f.x - a0);
    uint32_t l1 = pack_bf16x2(f.w - a3, f.z - a2);
    g_w_hi[i * 2]     = h0;
    g_w_hi[i * 2 + 1] = h1;
    g_w_lo[i * 2]     = l0;
    g_w_lo[i * 2 + 1] = l1;
}

#if HAS_TC
#define SWZ64(o) ((o) ^ (((o) >> 3) & 0x30))

// SW64 K-major descriptor: layout=4, version=1, SBO=32 (512B/8rows), LBO=1
__device__ __forceinline__ uint64_t mk_desc64(uint32_t addr) {
    const uint64_t base =
        (uint64_t(4) << 61) | (uint64_t(1) << 46) | (uint64_t(32) << 32) | (uint64_t(1) << 16);
    return base | ((uint64_t)(addr >> 4) & 0x3FFF);
}

// cg2 bf16 SS MMA (8-reg disable-lane vector, all zero)
__device__ __forceinline__ void mma_bf16_cg2(uint32_t d_tmem, uint64_t a_desc, uint64_t b_desc,
                                             uint32_t en) {
    uint32_t z = 0;
    asm volatile(
        "{\n\t.reg .pred p;\n\t"
        "setp.ne.u32 p, %5, 0;\n\t"
        "tcgen05.mma.cta_group::2.kind::f16 [%0], %1, %2, %3, "
        "{%4, %4, %4, %4, %4, %4, %4, %4}, p;\n\t}"
        :: "r"(d_tmem), "l"(a_desc), "l"(b_desc), "r"(IDESC_CG2), "r"(z), "r"(en)
        : "memory");
}

__device__ __forceinline__ void mbar_init(uint32_t mbar, uint32_t cnt) {
    asm volatile("mbarrier.init.shared.b64 [%0], %1;" :: "r"(mbar), "r"(cnt) : "memory");
}

__device__ __forceinline__ void mbar_wait(uint32_t mbar, uint32_t parity) {
    asm volatile(
        "{\n\t.reg .pred P;\n\t"
        "WL_%=:\n\t"
        "mbarrier.try_wait.parity.acquire.cta.shared::cta.b64 P, [%0], %1, 0x989680;\n\t"
        "@P bra.uni WD_%=;\n\t"
        "bra.uni WL_%=;\n\t"
        "WD_%=:\n\t}"
        :: "r"(mbar), "r"(parity) : "memory");
}

// acquire at cluster scope (consumer of peer-CTA release-arrives)
__device__ __forceinline__ void mbar_wait_cluster(uint32_t mbar, uint32_t parity) {
    asm volatile(
        "{\n\t.reg .pred P;\n\t"
        "WL_%=:\n\t"
        "mbarrier.try_wait.parity.acquire.cluster.shared::cta.b64 P, [%0], %1, 0x989680;\n\t"
        "@P bra.uni WD_%=;\n\t"
        "bra.uni WL_%=;\n\t"
        "WD_%=:\n\t}"
        :: "r"(mbar), "r"(parity) : "memory");
}

// release-arrive on rank0's mbarrier (mapa to rank 0)
__device__ __forceinline__ void mbar_arrive_rank0(uint32_t mbar) {
    asm volatile(
        "{\n\t.reg .b32 ra;\n\t"
        "mapa.shared::cluster.u32 ra, %0, 0;\n\t"
        "mbarrier.arrive.release.cluster.shared::cluster.b64 _, [ra];\n\t}"
        :: "r"(mbar) : "memory");
}

#define TC_ALLOC_CG2(dst_smem, n) \
    asm volatile("tcgen05.alloc.cta_group::2.sync.aligned.shared::cta.b32 [%0], %1;" \
                 :: "r"(dst_smem), "r"((uint32_t)(n)) : "memory")
#define TC_RELINQ_CG2() \
    asm volatile("tcgen05.relinquish_alloc_permit.cta_group::2.sync.aligned;")
#define TC_DEALLOC_CG2(tm, n) \
    asm volatile("tcgen05.dealloc.cta_group::2.sync.aligned.b32 %0, %1;" :: "r"(tm), "r"((uint32_t)(n)))
#define TC_COMMIT_MC_CG2(mbar, mask) \
    asm volatile("tcgen05.commit.cta_group::2.mbarrier::arrive::one.shared::cluster" \
                 ".multicast::cluster.b64 [%0], %1;" \
                 :: "r"(mbar), "h"((uint16_t)(mask)) : "memory")
#define TC_FENCE_AFTER()  asm volatile("tcgen05.fence::after_thread_sync;" ::: "memory")
#define TC_FENCE_BEFORE() asm volatile("tcgen05.fence::before_thread_sync;" ::: "memory")
#define FENCE_ASYNC() asm volatile("fence.proxy.async.shared::cta;" ::: "memory")
#define TC_WAIT_LD()  asm volatile("tcgen05.wait::ld.sync.aligned;" ::: "memory")
#define CLUSTER_SYNC() do { \
    asm volatile("barrier.cluster.arrive.aligned;" ::: "memory"); \
    asm volatile("barrier.cluster.wait.aligned;" ::: "memory"); } while (0)

#define TC_LD_X32(r, addr) \
    asm volatile( \
        "tcgen05.ld.sync.aligned.32x32b.x32.b32 " \
        "{%0, %1, %2, %3, %4, %5, %6, %7, " \
        " %8, %9, %10, %11, %12, %13, %14, %15, " \
        " %16, %17, %18, %19, %20, %21, %22, %23, " \
        " %24, %25, %26, %27, %28, %29, %30, %31}, [%32];" \
        : "=r"((r)[0]),  "=r"((r)[1]),  "=r"((r)[2]),  "=r"((r)[3]), \
          "=r"((r)[4]),  "=r"((r)[5]),  "=r"((r)[6]),  "=r"((r)[7]), \
          "=r"((r)[8]),  "=r"((r)[9]),  "=r"((r)[10]), "=r"((r)[11]), \
          "=r"((r)[12]), "=r"((r)[13]), "=r"((r)[14]), "=r"((r)[15]), \
          "=r"((r)[16]), "=r"((r)[17]), "=r"((r)[18]), "=r"((r)[19]), \
          "=r"((r)[20]), "=r"((r)[21]), "=r"((r)[22]), "=r"((r)[23]), \
          "=r"((r)[24]), "=r"((r)[25]), "=r"((r)[26]), "=r"((r)[27]), \
          "=r"((r)[28]), "=r"((r)[29]), "=r"((r)[30]), "=r"((r)[31]) \
        : "r"(addr))
#endif  // HAS_TC

extern __shared__ char g_dyn_smem[];

__global__ __launch_bounds__(256, 1) __cluster_dims__(2, 1, 1)
void gemm_kernel(const float* __restrict__ A,   // [T, D]
                 const float* __restrict__ W,   // [E, D] fp32 (fallback only)
                 float* __restrict__ C,         // [T, E]
                 int D, int E) {
#if HAS_TC
    // ================= cg2 bf16x3: M=256 per 2-CTA pair =====================
    __shared__ uint32_t s_tmem;
    __shared__ __align__(16) unsigned long long s_mbar[2 * NSTAGE];  // FULL, EMPT

    const int tid  = threadIdx.x;
    const int wid  = tid >> 5;
    const int lane = tid & 31;
    uint32_t rank;
    asm("mov.u32 %0, %%cluster_ctarank;" : "=r"(rank));

    uint32_t raw_u32  = smem_u32(g_dyn_smem);
    uint32_t tile_u32 = (raw_u32 + 1023u) & ~1023u;
    char*    tile_gen = g_dyn_smem + (tile_u32 - raw_u32);

    const uint32_t mb   = smem_u32(&s_mbar[0]);
    const uint32_t FULL = mb;            // on rank0: producer arrivals (count 2)
    const uint32_t EMPT = mb + 8 * NSTAGE;

    if (wid == 0) TC_ALLOC_CG2(smem_u32(&s_tmem), TMEM_NCOLS);
    if (tid == 0) {
        #pragma unroll
        for (int s = 0; s < NSTAGE; s++) {
            mbar_init(FULL + s * 8, 2);   // one arrive per CTA of the pair
            mbar_init(EMPT + s * 8, 1);   // commit multicast: arrive::one
        }
    }
    __syncthreads();
    CLUSTER_SYNC();   // mbars + TMEM alloc visible cluster-wide
    const uint32_t tmem = s_tmem;

    const int blockRow = blockIdx.x * BM;   // CTA's own 128 token rows

    // A producer mapping: group grp = tid>>3 (0..31), f4 column c4 = tid&7
    const int grp = tid >> 3;
    const int c4  = tid & 7;
    const float* aBase = A + (size_t)(blockRow + grp) * D + c4 * 4;
    const size_t rstep = (size_t)32 * D;
    const uint32_t rowOff = (uint32_t)(grp * 64 + c4 * 8);

    // B mapping (cg2 split): SMEM row j = h*64 + q holds expert h*128 + rank*64 + q.
    // thread: q = tid>>2 (0..63), ck = tid&3 (16B chunk), h = rr in {0,1}.
    const int q_  = tid >> 2;
    const int ck  = tid & 3;
    const char* whBase = (const char*)g_w_hi + ((size_t)(rank * 64 + q_)) * D * 2 + ck * 16;
    const char* wlBase = (const char*)g_w_lo + ((size_t)(rank * 64 + q_)) * D * 2 + ck * 16;
    const size_t bhstep = (size_t)128 * D * 2;     // +128 experts between halves
    const uint32_t bOff = (uint32_t)(q_ * 64 + ck * 16);

    const int niter = D / BKF;   // 128

    float4 bufA[4];
    uint4  bufBh[2], bufBl[2];
    #pragma unroll
    for (int qq = 0; qq < 4; qq++) bufA[qq] = *(const float4*)(aBase + qq * rstep);
    #pragma unroll
    for (int rr = 0; rr < 2; rr++) {
        bufBh[rr] = *(const uint4*)(whBase + rr * bhstep);
        bufBl[rr] = *(const uint4*)(wlBase + rr * bhstep);
    }

    for (int i = 0; i < niter; i++) {
        const int s = i & 3;
        const int r = i >> 2;
        const uint32_t stage = (uint32_t)s * STAGE_BYTES;

        if (r > 0) mbar_wait(EMPT + s * 8, (r - 1) & 1);

        // ---- B: swizzled STS of prefetched bf16 plane halves (no ALU) ----
        #pragma unroll
        for (int rr = 0; rr < 2; rr++) {
            const uint32_t off = SWZ64(bOff + (uint32_t)rr * 4096);  // h block = 64 rows
            *(uint4*)(tile_gen + stage + B_HI_OFF + off) = bufBh[rr];
            *(uint4*)(tile_gen + stage + B_LO_OFF + off) = bufBl[rr];
        }

        // ---- A: convert fp32 -> (hi, lo) bf16, swizzled STS ----
        #pragma unroll
        for (int qq = 0; qq < 4; qq++) {
            const uint32_t off = SWZ64(rowOff + (uint32_t)qq * 2048);
            float4 f = bufA[qq];
            uint32_t h0 = pack_bf16x2(f.y, f.x);
            uint32_t h1 = pack_bf16x2(f.w, f.z);
            float a0 = __uint_as_float(h0 << 16);
            float a1 = __uint_as_float(h0 & 0xFFFF0000u);
            float a2 = __uint_as_float(h1 << 16);
            float a3 = __uint_as_float(h1 & 0xFFFF0000u);
            uint32_t l0 = pack_bf16x2(f.y - a1, f.x - a0);
            uint32_t l1 = pack_bf16x2(f.w - a3, f.z - a2);
            *(uint2*)(tile_gen + stage + A_HI_OFF + off) = make_uint2(h0, h1);
            *(uint2*)(tile_gen + stage + A_LO_OFF + off) = make_uint2(l0, l1);
        }

        // ---- prefetch next K-chunk ----
        if (i + 1 < niter) {
            const int kt = (i + 1) * BKF;
            #pragma unroll
            for (int qq = 0; qq < 4; qq++) bufA[qq] = *(const float4*)(aBase + qq * rstep + kt);
            const size_t koff = (size_t)(i + 1) * 64;
            #pragma unroll
            for (int rr = 0; rr < 2; rr++) {
                bufBh[rr] = *(const uint4*)(whBase + rr * bhstep + koff);
                bufBl[rr] = *(const uint4*)(wlBase + rr * bhstep + koff);
            }
        }

        __syncthreads();

        // both CTAs signal stage ready on rank0's FULL
        if (tid == 0) {
            FENCE_ASYNC();
            mbar_arrive_rank0(FULL + s * 8);
        }

        // rank0 issues the cg2 MMAs
        if (rank == 0 && tid == 0) {
            mbar_wait_cluster(FULL + s * 8, r & 1);
            TC_FENCE_AFTER();
            const uint32_t sb = tile_u32 + stage;
            const uint64_t dAh = mk_desc64(sb + A_HI_OFF);
            const uint64_t dAl = mk_desc64(sb + A_LO_OFF);
            const uint64_t dBh = mk_desc64(sb + B_HI_OFF);
            const uint64_t dBl = mk_desc64(sb + B_LO_OFF);
            const uint32_t en = (i != 0);
            #pragma unroll
            for (int ks = 0; ks < 2; ks++) {
                const uint64_t o = 2 * ks;              // 16 bf16 = 32B = 2 units
                #pragma unroll
                for (int h = 0; h < 2; h++) {
                    const uint32_t d  = tmem + (uint32_t)h * 128 + (uint32_t)ks * 256;
                    const uint64_t bo = 256 * h + o;    // h block: 64 rows = 4096B
                    mma_bf16_cg2(d, dAh + o, dBh + bo, en);
                    mma_bf16_cg2(d, dAh + o, dBl + bo, 1);
                    mma_bf16_cg2(d, dAl + o, dBh + bo, 1);
                }
            }
            TC_COMMIT_MC_CG2(EMPT + s * 8, 0x3);
        }
    }

    // drain: final round (31) commit per stage, parity 1
    #pragma unroll
    for (int s = 0; s < NSTAGE; s++) mbar_wait(EMPT + s * 8, 1);
    TC_FENCE_AFTER();

    // epilogue: CTA reads its own 128 TMEM lanes. C[m, h*128+c] = D(h,0)+D(h,1)
    {
        const int m = blockRow + (wid & 3) * 32 + lane;
        const int h = wid >> 2;
        #pragma unroll
        for (int cb = 0; cb < 128; cb += 32) {
            uint32_t r0[32], r1[32];
            TC_LD_X32(r0, tmem + (uint32_t)h * 128 + cb);
            TC_LD_X32(r1, tmem + 256 + (uint32_t)h * 128 + cb);
            TC_WAIT_LD();
            float* cr = C + (size_t)m * E + h * 128 + cb;
            #pragma unroll
            for (int qq = 0; qq < 8; qq++) {
                float4 v = make_float4(
                    __uint_as_float(r0[qq * 4 + 0]) + __uint_as_float(r1[qq * 4 + 0]),
                    __uint_as_float(r0[qq * 4 + 1]) + __uint_as_float(r1[qq * 4 + 1]),
                    __uint_as_float(r0[qq * 4 + 2]) + __uint_as_float(r1[qq * 4 + 2]),
                    __uint_as_float(r0[qq * 4 + 3]) + __uint_as_float(r1[qq * 4 + 3]));
                *(float4*)(cr + qq * 4) = v;
            }
        }
        TC_FENCE_BEFORE();
    }
    __syncthreads();
    if (wid == 0) {
        TC_RELINQ_CG2();
        TC_DEALLOC_CG2(tmem, TMEM_NCOLS);
    }
    CLUSTER_SYNC();   // no CTA exits while peer MMA may still read its SMEM
#else
    // ==================== SIMT fp32 fallback ==================================
    __shared__ float As[BKF][128];
    __shared__ float Bs[BKF][128];

    const int tid = threadIdx.x;
    const int tx  = tid % 16;
    const int ty  = tid / 16;
    const int blockRow = blockIdx.x * BM;

    for (int half = 0; half < 2; half++) {
        const int blockCol = half * 128;
        const float* Ab = A + (size_t)blockRow * D;
        const float* Bb = W + (size_t)blockCol * D;

        float acc[8][8];
        #pragma unroll
        for (int i = 0; i < 8; i++)
            #pragma unroll
            for (int j = 0; j < 8; j++) acc[i][j] = 0.0f;

        const int lr = tid / 8;
        const int lc = tid % 8;

        for (int kt = 0; kt < D; kt += BKF) {
            __syncthreads();
            #pragma unroll
            for (int i = 0; i < 4; i++) {
                const int row = lr + i * 32;
                float4 va = *(const float4*)(Ab + (size_t)row * D + kt + lc * 4);
                As[lc * 4 + 0][row] = va.x;
                As[lc * 4 + 1][row] = va.y;
                As[lc * 4 + 2][row] = va.z;
                As[lc * 4 + 3][row] = va.w;
                float4 vb = *(const float4*)(Bb + (size_t)row * D + kt + lc * 4);
                Bs[lc * 4 + 0][row] = vb.x;
                Bs[lc * 4 + 1][row] = vb.y;
                Bs[lc * 4 + 2][row] = vb.z;
                Bs[lc * 4 + 3][row] = vb.w;
            }
            __syncthreads();

            #pragma unroll
            for (int k = 0; k < BKF; k++) {
                float a[8], b[8];
                *(float4*)&a[0] = *(const float4*)&As[k][ty * 8];
                *(float4*)&a[4] = *(const float4*)&As[k][ty * 8 + 4];
                *(float4*)&b[0] = *(const float4*)&Bs[k][tx * 8];
                *(float4*)&b[4] = *(const float4*)&Bs[k][tx * 8 + 4];
                #pragma unroll
                for (int i = 0; i < 8; i++)
                    #pragma unroll
                    for (int j = 0; j < 8; j++)
                        acc[i][j] = fmaf(a[i], b[j], acc[i][j]);
            }
        }

        #pragma unroll
        for (int i = 0; i < 8; i++) {
            const int row = blockRow + ty * 8 + i;
            float* Cr = C + (size_t)row * E + blockCol + tx * 8;
            *(float4*)(Cr + 0) = make_float4(acc[i][0], acc[i][1], acc[i][2], acc[i][3]);
            *(float4*)(Cr + 4) = make_float4(acc[i][4], acc[i][5], acc[i][6], acc[i][7]);
        }
        __syncthreads();
    }
#endif
}

// ---------------------------------------------------------------------------
// Router: warp per token; lane owns 8 experts (proven 18us version).
// ---------------------------------------------------------------------------
__global__ __launch_bounds__(256)
void router_topk_kernel(const float* __restrict__ C,
                        const float* __restrict__ bias,
                        float* __restrict__ wout,
                        float* __restrict__ iout) {
    const int t    = blockIdx.x * 8 + (threadIdx.x >> 5);
    const int lane = threadIdx.x & 31;

    const float4* row = (const float4*)(C + (size_t)t * 256) + lane * 2;
    float4 v0 = row[0], v1 = row[1];
    const float4* bp = (const float4*)bias + lane * 2;
    float4 b0 = __ldg(bp), b1 = __ldg(bp + 1);

    float sc[8] = {v0.x, v0.y, v0.z, v0.w, v1.x, v1.y, v1.z, v1.w};
    float bl[8] = {b0.x, b0.y, b0.z, b0.w, b1.x, b1.y, b1.z, b1.w};

    float m = sc[0];
    #pragma unroll
    for (int j = 1; j < 8; j++) m = fmaxf(m, sc[j]);
    #pragma unroll
    for (int off = 16; off > 0; off >>= 1)
        m = fmaxf(m, __shfl_xor_sync(0xffffffffu, m, off));

    float ex[8];
    float su = 0.0f;
    #pragma unroll
    for (int j = 0; j < 8; j++) { ex[j] = __expf(sc[j] - m); su += ex[j]; }
    #pragma unroll
    for (int off = 16; off > 0; off >>= 1)
        su += __shfl_xor_sync(0xffffffffu, su, off);
    const float inv = 1.0f / su;

    float prob[8], choice[8];
    #pragma unroll
    for (int j = 0; j < 8; j++) {
        prob[j]   = ex[j] * inv;
        choice[j] = prob[j] + bl[j];
    }

    float v = choice[0];
    int   li = 0;
    #pragma unroll
    for (int j = 1; j < 8; j++)
        if (choice[j] > v) { v = choice[j]; li = j; }

    #pragma unroll
    for (int k = 0; k < TOP_K; k++) {
        float g = v;
        #pragma unroll
        for (int off = 16; off > 0; off >>= 1)
            g = fmaxf(g, __shfl_xor_sync(0xffffffffu, g, off));
        unsigned mask = __ballot_sync(0xffffffffu, v == g);
        int src = __ffs(mask) - 1;
        if (lane == src) {
            float pw = 0.0f;
            #pragma unroll
            for (int j = 0; j < 8; j++)
                if (j == li) { pw = prob[j]; choice[j] = -INFINITY; }
            wout[(size_t)t * TOP_K + k] = pw * ROUTED_SCALE;
            iout[(size_t)t * TOP_K + k] = (float)(lane * 8 + li);
            v = choice[0]; li = 0;
            #pragma unroll
            for (int j = 1; j < 8; j++)
                if (choice[j] > v) { v = choice[j]; li = j; }
        }
    }
}

// ----------------------------- launch ---------------------------------------
extern "C" void kernel_launch(void* const* d_in, const int* in_sizes, int n_in,
                              void* d_out, int out_size) {
    const float* H    = (const float*)d_in[0];  // [T, D]
    const float* W    = (const float*)d_in[1];  // [E, D]
    const float* bias = (const float*)d_in[2];  // [E]

    const int E = in_sizes[2];                  // 256
    const int D = in_sizes[1] / E;              // 4096
    const int T = in_sizes[0] / D;              // 16384

    float* out  = (float*)d_out;
    float* C    = out;                          // [T, E]
    float* wout = out + (size_t)T * E;          // [T, 8]
    float* iout = wout + (size_t)T * TOP_K;     // [T, 8]

    static int attr_set = 0;
    if (!attr_set) {
        cudaFuncSetAttribute(gemm_kernel,
                             cudaFuncAttributeMaxDynamicSharedMemorySize, DYN_SMEM);
        attr_set = 1;
    }

    const int n4 = (E * D) / 4;
    split_w_kernel<<<(n4 + 511) / 512, 512>>>((const float4*)W, n4);
    gemm_kernel<<<T / BM, 256, DYN_SMEM>>>(H, W, C, D, E);
    router_topk_kernel<<<T / 8, 256>>>(C, bias, wout, iout);
}

// round 13
// speedup vs baseline: 1.1301x; 1.1301x over previous
#include <cuda_runtime.h>
#include <math.h>
#include <stdint.h>

// LongcatFlashTopkRouter: T=16384, D=4096, E=256
#define TOP_K 8
#define ROUTED_SCALE 1.5f

#if defined(__CUDA_ARCH__) && \
    (defined(__CUDA_ARCH_FEAT_SM103_ALL) || defined(__CUDA_ARCH_FEAT_SM100_ALL) || \
     defined(__CUDA_ARCH_FEAT_SM101_ALL))
#define HAS_TC 1
#else
#define HAS_TC 0
#endif

// ---------------------------------------------------------------------------
// GEMM via bf16x3 on tcgen05, 2 CTAs per SM (N-split).
// CTA tile: BM=128 tokens x BN=128 experts (half of E) x BK=32 floats.
// Grid = 256 CTAs -> 2 co-resident CTAs/SM for latency hiding.
// W pre-split to bf16 hi/lo planes; producers use register prefetch (R11).
// ---------------------------------------------------------------------------
#define BM 128
#define BKF 32
#define NSTAGE 3
#define A_HI_OFF 0
#define A_LO_OFF 8192
#define B_HI_OFF 16384
#define B_LO_OFF 24576
#define STAGE_BYTES 32768
#define DYN_SMEM (NSTAGE * STAGE_BYTES + 1024)   // 99328 B -> 2 CTAs fit in 228KB

// idesc kind::f16 bf16: F32(1)<<4 | BF16(1)<<7 | BF16(1)<<10 | (N=128/8)<<17 | (M=128/16)<<24
#define IDESC 0x8200490u
#define TMEM_NCOLS 256
// accumulators: D(ks) at col ks*128

// W split into bf16 hi/lo planes, once per launch (2MB each).
__device__ __align__(1024) static uint32_t g_w_hi[524288];
__device__ __align__(1024) static uint32_t g_w_lo[524288];

__device__ __forceinline__ uint32_t pack_bf16x2(float hi, float lo) {
    uint32_t d;
    asm("cvt.rn.bf16x2.f32 %0, %1, %2;" : "=r"(d) : "f"(hi), "f"(lo));
    return d;
}

__device__ __forceinline__ uint32_t smem_u32(const void* p) {
    uint32_t a;
    asm("{ .reg .u64 t; cvta.to.shared.u64 t, %1; cvt.u32.u64 %0, t; }" : "=r"(a) : "l"(p));
    return a;
}

// ------------------------- prep: split W fp32 -> bf16 hi/lo ------------------
__global__ __launch_bounds__(512)
void split_w_kernel(const float4* __restrict__ W4, int n4) {
    int i = blockIdx.x * 512 + threadIdx.x;
    if (i >= n4) return;
    float4 f = W4[i];
    uint32_t h0 = pack_bf16x2(f.y, f.x);
    uint32_t h1 = pack_bf16x2(f.w, f.z);
    float a0 = __uint_as_float(h0 << 16);
    float a1 = __uint_as_float(h0 & 0xFFFF0000u);
    float a2 = __uint_as_float(h1 << 16);
    float a3 = __uint_as_float(h1 & 0xFFFF0000u);
    uint32_t l0 = pack_bf16x2(f.y - a1, f.x - a0);
    uint32_t l1 = pack_bf16x2(f.w - a3, f.z - a2);
    g_w_hi[i * 2]     = h0;
    g_w_hi[i * 2 + 1] = h1;
    g_w_lo[i * 2]     = l0;
    g_w_lo[i * 2 + 1] = l1;
}

#if HAS_TC
#define SWZ64(o) ((o) ^ (((o) >> 3) & 0x30))

// SW64 K-major descriptor: layout=4, version=1, SBO=32 (512B/8rows), LBO=1
__device__ __forceinline__ uint64_t mk_desc64(uint32_t addr) {
    const uint64_t base =
        (uint64_t(4) << 61) | (uint64_t(1) << 46) | (uint64_t(32) << 32) | (uint64_t(1) << 16);
    return base | ((uint64_t)(addr >> 4) & 0x3FFF);
}

__device__ __forceinline__ void mma_bf16_ss(uint32_t d_tmem, uint64_t a_desc, uint64_t b_desc,
                                            uint32_t en) {
    uint32_t z = 0;
    asm volatile(
        "{\n\t.reg .pred p;\n\t"
        "setp.ne.u32 p, %5, 0;\n\t"
        "tcgen05.mma.cta_group::1.kind::f16 [%0], %1, %2, %3, {%4, %4, %4, %4}, p;\n\t}"
        :: "r"(d_tmem), "l"(a_desc), "l"(b_desc), "r"(IDESC), "r"(z), "r"(en)
        : "memory");
}

__device__ __forceinline__ void mbar_init(uint32_t mbar, uint32_t cnt) {
    asm volatile("mbarrier.init.shared.b64 [%0], %1;" :: "r"(mbar), "r"(cnt) : "memory");
}

__device__ __forceinline__ void mbar_wait(uint32_t mbar, uint32_t parity) {
    asm volatile(
        "{\n\t.reg .pred P;\n\t"
        "WL_%=:\n\t"
        "mbarrier.try_wait.parity.acquire.cta.shared::cta.b64 P, [%0], %1, 0x989680;\n\t"
        "@P bra.uni WD_%=;\n\t"
        "bra.uni WL_%=;\n\t"
        "WD_%=:\n\t}"
        :: "r"(mbar), "r"(parity) : "memory");
}

#define TC_ALLOC(dst_smem, n) \
    asm volatile("tcgen05.alloc.cta_group::1.sync.aligned.shared::cta.b32 [%0], %1;" \
                 :: "r"(dst_smem), "r"((uint32_t)(n)) : "memory")
#define TC_RELINQ() \
    asm volatile("tcgen05.relinquish_alloc_permit.cta_group::1.sync.aligned;")
#define TC_DEALLOC(tm, n) \
    asm volatile("tcgen05.dealloc.cta_group::1.sync.aligned.b32 %0, %1;" :: "r"(tm), "r"((uint32_t)(n)))
#define TC_COMMIT(mbar) \
    asm volatile("tcgen05.commit.cta_group::1.mbarrier::arrive::one.shared::cluster.b64 [%0];" \
                 :: "r"(mbar) : "memory")
#define TC_FENCE_AFTER()  asm volatile("tcgen05.fence::after_thread_sync;" ::: "memory")
#define TC_FENCE_BEFORE() asm volatile("tcgen05.fence::before_thread_sync;" ::: "memory")
#define FENCE_ASYNC() asm volatile("fence.proxy.async.shared::cta;" ::: "memory")
#define TC_WAIT_LD()  asm volatile("tcgen05.wait::ld.sync.aligned;" ::: "memory")

#define TC_LD_X32(r, addr) \
    asm volatile( \
        "tcgen05.ld.sync.aligned.32x32b.x32.b32 " \
        "{%0, %1, %2, %3, %4, %5, %6, %7, " \
        " %8, %9, %10, %11, %12, %13, %14, %15, " \
        " %16, %17, %18, %19, %20, %21, %22, %23, " \
        " %24, %25, %26, %27, %28, %29, %30, %31}, [%32];" \
        : "=r"((r)[0]),  "=r"((r)[1]),  "=r"((r)[2]),  "=r"((r)[3]), \
          "=r"((r)[4]),  "=r"((r)[5]),  "=r"((r)[6]),  "=r"((r)[7]), \
          "=r"((r)[8]),  "=r"((r)[9]),  "=r"((r)[10]), "=r"((r)[11]), \
          "=r"((r)[12]), "=r"((r)[13]), "=r"((r)[14]), "=r"((r)[15]), \
          "=r"((r)[16]), "=r"((r)[17]), "=r"((r)[18]), "=r"((r)[19]), \
          "=r"((r)[20]), "=r"((r)[21]), "=r"((r)[22]), "=r"((r)[23]), \
          "=r"((r)[24]), "=r"((r)[25]), "=r"((r)[26]), "=r"((r)[27]), \
          "=r"((r)[28]), "=r"((r)[29]), "=r"((r)[30]), "=r"((r)[31]) \
        : "r"(addr))
#endif  // HAS_TC

extern __shared__ char g_dyn_smem[];

__global__ __launch_bounds__(256, 2)
void gemm_kernel(const float* __restrict__ A,   // [T, D]
                 const float* __restrict__ W,   // [E, D] fp32 (fallback only)
                 float* __restrict__ C,         // [T, E]
                 int D, int E) {
#if HAS_TC
    // ========== tcgen05 bf16x3, N-split tiles, 2 CTAs per SM ================
    __shared__ uint32_t s_tmem;
    __shared__ __align__(16) unsigned long long s_mbar[NSTAGE];

    const int tid  = threadIdx.x;
    const int wid  = tid >> 5;
    const int lane = tid & 31;

    uint32_t raw_u32  = smem_u32(g_dyn_smem);
    uint32_t tile_u32 = (raw_u32 + 1023u) & ~1023u;
    char*    tile_gen = g_dyn_smem + (tile_u32 - raw_u32);

    const uint32_t mbar_u32 = smem_u32(&s_mbar[0]);

    if (wid == 0) {
        TC_ALLOC(smem_u32(&s_tmem), TMEM_NCOLS);
        TC_RELINQ();   // let the co-resident CTA allocate immediately
    }
    if (tid == 0) {
        mbar_init(mbar_u32, 1);
        mbar_init(mbar_u32 + 8, 1);
        mbar_init(mbar_u32 + 16, 1);
    }
    __syncthreads();
    const uint32_t tmem = s_tmem;

    const int blockRow = (blockIdx.x >> 1) * BM;        // token tile
    const int eBase    = (blockIdx.x & 1) * 128;        // expert half

    // A producer mapping: group grp = tid>>3 (0..31), f4 column c4 = tid&7
    const int grp = tid >> 3;
    const int c4  = tid & 7;
    const float* aBase = A + (size_t)(blockRow + grp) * D + c4 * 4;
    const size_t rstep = (size_t)32 * D;
    const uint32_t rowOff = (uint32_t)(grp * 64 + c4 * 8);

    // B mapping (bf16 planes, 128 rows): row = tid>>1, 32B piece = (tid&1)*32
    const int brow = tid >> 1;
    const int bck  = (tid & 1) * 32;
    const char* whBase = (const char*)g_w_hi + (size_t)(eBase + brow) * D * 2 + bck;
    const char* wlBase = (const char*)g_w_lo + (size_t)(eBase + brow) * D * 2 + bck;
    const uint32_t bOff = (uint32_t)(brow * 64 + bck);

    const int niter = D / BKF;   // 128
    int ph0 = 0, ph1 = 0, ph2 = 0;
    int s = 0;

    float4 bufA[4];
    uint4  bufBh[2], bufBl[2];
    #pragma unroll
    for (int q = 0; q < 4; q++) bufA[q] = *(const float4*)(aBase + q * rstep);
    bufBh[0] = *(const uint4*)(whBase);
    bufBh[1] = *(const uint4*)(whBase + 16);
    bufBl[0] = *(const uint4*)(wlBase);
    bufBl[1] = *(const uint4*)(wlBase + 16);

    for (int i = 0; i < niter; i++) {
        const uint32_t stage = (uint32_t)s * STAGE_BYTES;

        if (i >= NSTAGE) {
            if      (s == 0) { mbar_wait(mbar_u32,      ph0); ph0 ^= 1; }
            else if (s == 1) { mbar_wait(mbar_u32 + 8,  ph1); ph1 ^= 1; }
            else             { mbar_wait(mbar_u32 + 16, ph2); ph2 ^= 1; }
        }

        // ---- B: swizzled STS of prefetched plane data (no ALU) ----
        *(uint4*)(tile_gen + stage + B_HI_OFF + SWZ64(bOff))      = bufBh[0];
        *(uint4*)(tile_gen + stage + B_HI_OFF + SWZ64(bOff + 16)) = bufBh[1];
        *(uint4*)(tile_gen + stage + B_LO_OFF + SWZ64(bOff))      = bufBl[0];
        *(uint4*)(tile_gen + stage + B_LO_OFF + SWZ64(bOff + 16)) = bufBl[1];

        // ---- A: convert fp32 -> (hi, lo) bf16, swizzled STS ----
        #pragma unroll
        for (int q = 0; q < 4; q++) {
            const uint32_t off = SWZ64(rowOff + (uint32_t)q * 2048);
            float4 f = bufA[q];
            uint32_t h0 = pack_bf16x2(f.y, f.x);
            uint32_t h1 = pack_bf16x2(f.w, f.z);
            float a0 = __uint_as_float(h0 << 16);
            float a1 = __uint_as_float(h0 & 0xFFFF0000u);
            float a2 = __uint_as_float(h1 << 16);
            float a3 = __uint_as_float(h1 & 0xFFFF0000u);
            uint32_t l0 = pack_bf16x2(f.y - a1, f.x - a0);
            uint32_t l1 = pack_bf16x2(f.w - a3, f.z - a2);
            *(uint2*)(tile_gen + stage + A_HI_OFF + off) = make_uint2(h0, h1);
            *(uint2*)(tile_gen + stage + A_LO_OFF + off) = make_uint2(l0, l1);
        }

        // ---- prefetch next K-chunk ----
        if (i + 1 < niter) {
            const int kt = (i + 1) * BKF;
            #pragma unroll
            for (int q = 0; q < 4; q++) bufA[q] = *(const float4*)(aBase + q * rstep + kt);
            const size_t koff = (size_t)(i + 1) * 64;
            bufBh[0] = *(const uint4*)(whBase + koff);
            bufBh[1] = *(const uint4*)(whBase + koff + 16);
            bufBl[0] = *(const uint4*)(wlBase + koff);
            bufBl[1] = *(const uint4*)(wlBase + koff + 16);
        }

        __syncthreads();

        if (tid == 0) {
            FENCE_ASYNC();
            const uint32_t sb = tile_u32 + stage;
            const uint64_t dAh = mk_desc64(sb + A_HI_OFF);
            const uint64_t dAl = mk_desc64(sb + A_LO_OFF);
            const uint64_t dBh = mk_desc64(sb + B_HI_OFF);
            const uint64_t dBl = mk_desc64(sb + B_LO_OFF);
            const uint32_t en = (i != 0);
            // 2 independent chains: D(ks) at tmem + ks*128
            #pragma unroll
            for (int ks = 0; ks < 2; ks++) {
                const uint64_t o = 2 * ks;           // 16 bf16 = 32B = 2 units
                const uint32_t d = tmem + (uint32_t)ks * 128;
                mma_bf16_ss(d, dAh + o, dBh + o, en);
                mma_bf16_ss(d, dAh + o, dBl + o, 1);
                mma_bf16_ss(d, dAl + o, dBh + o, 1);
            }
            if      (s == 0) TC_COMMIT(mbar_u32);
            else if (s == 1) TC_COMMIT(mbar_u32 + 8);
            else             TC_COMMIT(mbar_u32 + 16);
        }

        s = (s == NSTAGE - 1) ? 0 : s + 1;
    }

    mbar_wait(mbar_u32,      ph0);
    mbar_wait(mbar_u32 + 8,  ph1);
    mbar_wait(mbar_u32 + 16, ph2);
    TC_FENCE_AFTER();

    // epilogue: 8 warps; warp covers col quarter h = wid>>2 (64 cols), rows
    // (wid&3)*32+lane. C[m, eBase+c] = D(0)[c] + D(1)[c]
    {
        const int m  = blockRow + (wid & 3) * 32 + lane;
        const int c0 = (wid >> 2) * 64;
        #pragma unroll
        for (int cb = 0; cb < 64; cb += 32) {
            uint32_t r0[32], r1[32];
            TC_LD_X32(r0, tmem + c0 + cb);
            TC_LD_X32(r1, tmem + 128 + c0 + cb);
            TC_WAIT_LD();
            float* cr = C + (size_t)m * E + eBase + c0 + cb;
            #pragma unroll
            for (int q = 0; q < 8; q++) {
                float4 v = make_float4(
                    __uint_as_float(r0[q * 4 + 0]) + __uint_as_float(r1[q * 4 + 0]),
                    __uint_as_float(r0[q * 4 + 1]) + __uint_as_float(r1[q * 4 + 1]),
                    __uint_as_float(r0[q * 4 + 2]) + __uint_as_float(r1[q * 4 + 2]),
                    __uint_as_float(r0[q * 4 + 3]) + __uint_as_float(r1[q * 4 + 3]));
                *(float4*)(cr + q * 4) = v;
            }
        }
        TC_FENCE_BEFORE();
    }
    __syncthreads();
    if (wid == 0) {
        TC_DEALLOC(tmem, TMEM_NCOLS);
    }
#else
    // ==================== SIMT fp32 fallback (N-split grid) ==================
    __shared__ float As[BKF][128];
    __shared__ float Bs[BKF][128];

    const int tid = threadIdx.x;
    const int tx  = tid % 16;
    const int ty  = tid / 16;
    const int blockRow = (blockIdx.x >> 1) * BM;
    const int blockCol = (blockIdx.x & 1) * 128;

    const float* Ab = A + (size_t)blockRow * D;
    const float* Bb = W + (size_t)blockCol * D;

    float acc[8][8];
    #pragma unroll
    for (int i = 0; i < 8; i++)
        #pragma unroll
        for (int j = 0; j < 8; j++) acc[i][j] = 0.0f;

    const int lr = tid / 8;
    const int lc = tid % 8;

    for (int kt = 0; kt < D; kt += BKF) {
        __syncthreads();
        #pragma unroll
        for (int i = 0; i < 4; i++) {
            const int row = lr + i * 32;
            float4 va = *(const float4*)(Ab + (size_t)row * D + kt + lc * 4);
            As[lc * 4 + 0][row] = va.x;
            As[lc * 4 + 1][row] = va.y;
            As[lc * 4 + 2][row] = va.z;
            As[lc * 4 + 3][row] = va.w;
            float4 vb = *(const float4*)(Bb + (size_t)row * D + kt + lc * 4);
            Bs[lc * 4 + 0][row] = vb.x;
            Bs[lc * 4 + 1][row] = vb.y;
            Bs[lc * 4 + 2][row] = vb.z;
            Bs[lc * 4 + 3][row] = vb.w;
        }
        __syncthreads();

        #pragma unroll
        for (int k = 0; k < BKF; k++) {
            float a[8], b[8];
            *(float4*)&a[0] = *(const float4*)&As[k][ty * 8];
            *(float4*)&a[4] = *(const float4*)&As[k][ty * 8 + 4];
            *(float4*)&b[0] = *(const float4*)&Bs[k][tx * 8];
            *(float4*)&b[4] = *(const float4*)&Bs[k][tx * 8 + 4];
            #pragma unroll
            for (int i = 0; i < 8; i++)
                #pragma unroll
                for (int j = 0; j < 8; j++)
                    acc[i][j] = fmaf(a[i], b[j], acc[i][j]);
        }
    }

    #pragma unroll
    for (int i = 0; i < 8; i++) {
        const int row = blockRow + ty * 8 + i;
        float* Cr = C + (size_t)row * E + blockCol + tx * 8;
        *(float4*)(Cr + 0) = make_float4(acc[i][0], acc[i][1], acc[i][2], acc[i][3]);
        *(float4*)(Cr + 4) = make_float4(acc[i][4], acc[i][5], acc[i][6], acc[i][7]);
    }
#endif
}

// ---------------------------------------------------------------------------
// Router: warp per token; lane owns 8 experts (proven 18us version).
// ---------------------------------------------------------------------------
__global__ __launch_bounds__(256)
void router_topk_kernel(const float* __restrict__ C,
                        const float* __restrict__ bias,
                        float* __restrict__ wout,
                        float* __restrict__ iout) {
    const int t    = blockIdx.x * 8 + (threadIdx.x >> 5);
    const int lane = threadIdx.x & 31;

    const float4* row = (const float4*)(C + (size_t)t * 256) + lane * 2;
    float4 v0 = row[0], v1 = row[1];
    const float4* bp = (const float4*)bias + lane * 2;
    float4 b0 = __ldg(bp), b1 = __ldg(bp + 1);

    float sc[8] = {v0.x, v0.y, v0.z, v0.w, v1.x, v1.y, v1.z, v1.w};
    float bl[8] = {b0.x, b0.y, b0.z, b0.w, b1.x, b1.y, b1.z, b1.w};

    float m = sc[0];
    #pragma unroll
    for (int j = 1; j < 8; j++) m = fmaxf(m, sc[j]);
    #pragma unroll
    for (int off = 16; off > 0; off >>= 1)
        m = fmaxf(m, __shfl_xor_sync(0xffffffffu, m, off));

    float ex[8];
    float su = 0.0f;
    #pragma unroll
    for (int j = 0; j < 8; j++) { ex[j] = __expf(sc[j] - m); su += ex[j]; }
    #pragma unroll
    for (int off = 16; off > 0; off >>= 1)
        su += __shfl_xor_sync(0xffffffffu, su, off);
    const float inv = 1.0f / su;

    float prob[8], choice[8];
    #pragma unroll
    for (int j = 0; j < 8; j++) {
        prob[j]   = ex[j] * inv;
        choice[j] = prob[j] + bl[j];
    }

    float v = choice[0];
    int   li = 0;
    #pragma unroll
    for (int j = 1; j < 8; j++)
        if (choice[j] > v) { v = choice[j]; li = j; }

    #pragma unroll
    for (int k = 0; k < TOP_K; k++) {
        float g = v;
        #pragma unroll
        for (int off = 16; off > 0; off >>= 1)
            g = fmaxf(g, __shfl_xor_sync(0xffffffffu, g, off));
        unsigned mask = __ballot_sync(0xffffffffu, v == g);
        int src = __ffs(mask) - 1;
        if (lane == src) {
            float pw = 0.0f;
            #pragma unroll
            for (int j = 0; j < 8; j++)
                if (j == li) { pw = prob[j]; choice[j] = -INFINITY; }
            wout[(size_t)t * TOP_K + k] = pw * ROUTED_SCALE;
            iout[(size_t)t * TOP_K + k] = (float)(lane * 8 + li);
            v = choice[0]; li = 0;
            #pragma unroll
            for (int j = 1; j < 8; j++)
                if (choice[j] > v) { v = choice[j]; li = j; }
        }
    }
}

// ----------------------------- launch ---------------------------------------
extern "C" void kernel_launch(void* const* d_in, const int* in_sizes, int n_in,
                              void* d_out, int out_size) {
    const float* H    = (const float*)d_in[0];  // [T, D]
    const float* W    = (const float*)d_in[1];  // [E, D]
    const float* bias = (const float*)d_in[2];  // [E]

    const int E = in_sizes[2];                  // 256
    const int D = in_sizes[1] / E;              // 4096
    const int T = in_sizes[0] / D;              // 16384

    float* out  = (float*)d_out;
    float* C    = out;                          // [T, E]
    float* wout = out + (size_t)T * E;          // [T, 8]
    float* iout = wout + (size_t)T * TOP_K;     // [T, 8]

    static int attr_set = 0;
    if (!attr_set) {
        cudaFuncSetAttribute(gemm_kernel,
                             cudaFuncAttributeMaxDynamicSharedMemorySize, DYN_SMEM);
        attr_set = 1;
    }

    const int n4 = (E * D) / 4;
    split_w_kernel<<<(n4 + 511) / 512, 512>>>((const float4*)W, n4);
    gemm_kernel<<<2 * (T / BM), 256, DYN_SMEM>>>(H, W, C, D, E);
    router_topk_kernel<<<T / 8, 256>>>(C, bias, wout, iout);
}

// round 15
// speedup vs baseline: 1.6331x; 1.4451x over previous
#include <cuda_runtime.h>
#include <math.h>
#include <stdint.h>

// LongcatFlashTopkRouter: T=16384, D=4096, E=256
#define TOP_K 8
#define ROUTED_SCALE 1.5f

#if defined(__CUDA_ARCH__) && \
    (defined(__CUDA_ARCH_FEAT_SM103_ALL) || defined(__CUDA_ARCH_FEAT_SM100_ALL) || \
     defined(__CUDA_ARCH_FEAT_SM101_ALL))
#define HAS_TC 1
#else
#define HAS_TC 0
#endif

// ---------------------------------------------------------------------------
// GEMM: C[t,e] = dot(H[t,:], W[e,:]) via bf16x3 emulation on tcgen05.
// R9 champion core (4 accumulator chains) with NSTAGE=4 pipeline.
// ---------------------------------------------------------------------------
#define BM 128
#define BN 256
#define BKF 32
#define STAGE_BYTES 49152
#define A_HI_OFF 0
#define A_LO_OFF 8192
#define B_HI_OFF 16384
#define B_LO_OFF 32768
#define NSTAGE 4
#define DYN_SMEM (NSTAGE * STAGE_BYTES + 1024)

// idesc kind::f16 bf16: F32(1)<<4 | BF16(1)<<7 | BF16(1)<<10 | (N=128/8)<<17 | (M=128/16)<<24
#define IDESC 0x8200490u
#define TMEM_NCOLS 512
// D accumulators: D(h, ks) at col h*128 + ks*256

#if HAS_TC
__device__ __forceinline__ uint32_t smem_u32(const void* p) {
    uint32_t a;
    asm("{ .reg .u64 t; cvta.to.shared.u64 t, %1; cvt.u32.u64 %0, t; }" : "=r"(a) : "l"(p));
    return a;
}

// d = { upper = bf16(hi), lower = bf16(lo) }
__device__ __forceinline__ uint32_t pack_bf16x2(float hi, float lo) {
    uint32_t d;
    asm("cvt.rn.bf16x2.f32 %0, %1, %2;" : "=r"(d) : "f"(hi), "f"(lo));
    return d;
}

#define SWZ64(o) ((o) ^ (((o) >> 3) & 0x30))

// SW64 K-major descriptor: layout=4, version=1, SBO=32 (512B/8rows), LBO=1
__device__ __forceinline__ uint64_t mk_desc64(uint32_t addr) {
    const uint64_t base =
        (uint64_t(4) << 61) | (uint64_t(1) << 46) | (uint64_t(32) << 32) | (uint64_t(1) << 16);
    return base | ((uint64_t)(addr >> 4) & 0x3FFF);
}

__device__ __forceinline__ void mma_bf16_ss(uint32_t d_tmem, uint64_t a_desc, uint64_t b_desc,
                                            uint32_t en) {
    uint32_t z = 0;
    asm volatile(
        "{\n\t.reg .pred p;\n\t"
        "setp.ne.u32 p, %5, 0;\n\t"
        "tcgen05.mma.cta_group::1.kind::f16 [%0], %1, %2, %3, {%4, %4, %4, %4}, p;\n\t}"
        :: "r"(d_tmem), "l"(a_desc), "l"(b_desc), "r"(IDESC), "r"(z), "r"(en)
        : "memory");
}

__device__ __forceinline__ void mbar_init(uint32_t mbar, uint32_t cnt) {
    asm volatile("mbarrier.init.shared.b64 [%0], %1;" :: "r"(mbar), "r"(cnt) : "memory");
}

__device__ __forceinline__ void mbar_wait(uint32_t mbar, uint32_t parity) {
    asm volatile(
        "{\n\t.reg .pred P;\n\t"
        "WL_%=:\n\t"
        "mbarrier.try_wait.parity.acquire.cta.shared::cta.b64 P, [%0], %1, 0x989680;\n\t"
        "@P bra.uni WD_%=;\n\t"
        "bra.uni WL_%=;\n\t"
        "WD_%=:\n\t}"
        :: "r"(mbar), "r"(parity) : "memory");
}

#define TC_ALLOC(dst_smem, n) \
    asm volatile("tcgen05.alloc.cta_group::1.sync.aligned.shared::cta.b32 [%0], %1;" \
                 :: "r"(dst_smem), "r"((uint32_t)(n)) : "memory")
#define TC_RELINQ() \
    asm volatile("tcgen05.relinquish_alloc_permit.cta_group::1.sync.aligned;")
#define TC_DEALLOC(tm, n) \
    asm volatile("tcgen05.dealloc.cta_group::1.sync.aligned.b32 %0, %1;" :: "r"(tm), "r"((uint32_t)(n)))
#define TC_COMMIT(mbar) \
    asm volatile("tcgen05.commit.cta_group::1.mbarrier::arrive::one.shared::cluster.b64 [%0];" \
                 :: "r"(mbar) : "memory")
#define TC_FENCE_AFTER()  asm volatile("tcgen05.fence::after_thread_sync;" ::: "memory")
#define TC_FENCE_BEFORE() asm volatile("tcgen05.fence::before_thread_sync;" ::: "memory")
#define FENCE_ASYNC() asm volatile("fence.proxy.async.shared::cta;" ::: "memory")
#define TC_WAIT_LD()  asm volatile("tcgen05.wait::ld.sync.aligned;" ::: "memory")

#define TC_LD_X32(r, addr) \
    asm volatile( \
        "tcgen05.ld.sync.aligned.32x32b.x32.b32 " \
        "{%0, %1, %2, %3, %4, %5, %6, %7, " \
        " %8, %9, %10, %11, %12, %13, %14, %15, " \
        " %16, %17, %18, %19, %20, %21, %22, %23, " \
        " %24, %25, %26, %27, %28, %29, %30, %31}, [%32];" \
        : "=r"((r)[0]),  "=r"((r)[1]),  "=r"((r)[2]),  "=r"((r)[3]), \
          "=r"((r)[4]),  "=r"((r)[5]),  "=r"((r)[6]),  "=r"((r)[7]), \
          "=r"((r)[8]),  "=r"((r)[9]),  "=r"((r)[10]), "=r"((r)[11]), \
          "=r"((r)[12]), "=r"((r)[13]), "=r"((r)[14]), "=r"((r)[15]), \
          "=r"((r)[16]), "=r"((r)[17]), "=r"((r)[18]), "=r"((r)[19]), \
          "=r"((r)[20]), "=r"((r)[21]), "=r"((r)[22]), "=r"((r)[23]), \
          "=r"((r)[24]), "=r"((r)[25]), "=r"((r)[26]), "=r"((r)[27]), \
          "=r"((r)[28]), "=r"((r)[29]), "=r"((r)[30]), "=r"((r)[31]) \
        : "r"(addr))
#endif  // HAS_TC

extern __shared__ char g_dyn_smem[];

__global__ __launch_bounds__(256, 1)
void gemm_kernel(const float* __restrict__ A,   // [T, D]
                 const float* __restrict__ W,   // [E, D]
                 float* __restrict__ C,         // [T, E]
                 int D, int E) {
#if HAS_TC
    // ========= tcgen05 bf16x3, 4 accumulator chains, 4-stage pipeline ========
    __shared__ uint32_t s_tmem;
    __shared__ __align__(16) unsigned long long s_mbar[NSTAGE];

    const int tid  = threadIdx.x;
    const int wid  = tid >> 5;
    const int lane = tid & 31;

    uint32_t raw_u32  = smem_u32(g_dyn_smem);
    uint32_t tile_u32 = (raw_u32 + 1023u) & ~1023u;
    char*    tile_gen = g_dyn_smem + (tile_u32 - raw_u32);

    const uint32_t mbar_u32 = smem_u32(&s_mbar[0]);

    if (wid == 0) TC_ALLOC(smem_u32(&s_tmem), TMEM_NCOLS);
    if (tid == 0) {
        mbar_init(mbar_u32, 1);
        mbar_init(mbar_u32 + 8, 1);
        mbar_init(mbar_u32 + 16, 1);
        mbar_init(mbar_u32 + 24, 1);
    }
    __syncthreads();
    const uint32_t tmem = s_tmem;

    const int blockRow = blockIdx.x * BM;

    // producer mapping: group g = tid>>3 (0..31), f4 column tid&7 (0..7)
    const int grp = tid >> 3;
    const int c4  = tid & 7;

    const float* aBase = A + (size_t)(blockRow + grp) * D + c4 * 4;
    const float* bBase = W + (size_t)grp * D + c4 * 4;
    const size_t rstep = (size_t)32 * D;

    const int niter = D / BKF;   // 128
    int ph0 = 0, ph1 = 0, ph2 = 0, ph3 = 0;

    float4 bufA[4], bufB[8];
    #pragma unroll
    for (int q = 0; q < 4; q++) bufA[q] = *(const float4*)(aBase + q * rstep);
    #pragma unroll
    for (int p = 0; p < 8; p++) bufB[p] = *(const float4*)(bBase + p * rstep);

    const uint32_t rowOff = (uint32_t)(grp * 64 + c4 * 8);

    for (int i = 0; i < niter; i++) {
        const int s = i & 3;
        const uint32_t stage = (uint32_t)s * STAGE_BYTES;

        if (i >= NSTAGE) {
            if      (s == 0) { mbar_wait(mbar_u32,      ph0); ph0 ^= 1; }
            else if (s == 1) { mbar_wait(mbar_u32 + 8,  ph1); ph1 ^= 1; }
            else if (s == 2) { mbar_wait(mbar_u32 + 16, ph2); ph2 ^= 1; }
            else             { mbar_wait(mbar_u32 + 24, ph3); ph3 ^= 1; }
        }

        // convert fp32 -> (hi, lo) bf16, swizzled STS
        #pragma unroll
        for (int q = 0; q < 4; q++) {
            const uint32_t off = SWZ64(rowOff + (uint32_t)q * 2048);
            float4 f = bufA[q];
            uint32_t h0 = pack_bf16x2(f.y, f.x);
            uint32_t h1 = pack_bf16x2(f.w, f.z);
            float a0 = __uint_as_float(h0 << 16);
            float a1 = __uint_as_float(h0 & 0xFFFF0000u);
            float a2 = __uint_as_float(h1 << 16);
            float a3 = __uint_as_float(h1 & 0xFFFF0000u);
            uint32_t l0 = pack_bf16x2(f.y - a1, f.x - a0);
            uint32_t l1 = pack_bf16x2(f.w - a3, f.z - a2);
            *(uint2*)(tile_gen + stage + A_HI_OFF + off) = make_uint2(h0, h1);
            *(uint2*)(tile_gen + stage + A_LO_OFF + off) = make_uint2(l0, l1);
        }
        #pragma unroll
        for (int p = 0; p < 8; p++) {
            const uint32_t off = SWZ64(rowOff + (uint32_t)p * 2048);
            float4 f = bufB[p];
            uint32_t h0 = pack_bf16x2(f.y, f.x);
            uint32_t h1 = pack_bf16x2(f.w, f.z);
            float a0 = __uint_as_float(h0 << 16);
            float a1 = __uint_as_float(h0 & 0xFFFF0000u);
            float a2 = __uint_as_float(h1 << 16);
            float a3 = __uint_as_float(h1 & 0xFFFF0000u);
            uint32_t l0 = pack_bf16x2(f.y - a1, f.x - a0);
            uint32_t l1 = pack_bf16x2(f.w - a3, f.z - a2);
            *(uint2*)(tile_gen + stage + B_HI_OFF + off) = make_uint2(h0, h1);
            *(uint2*)(tile_gen + stage + B_LO_OFF + off) = make_uint2(l0, l1);
        }

        if (i + 1 < niter) {
            const int kt = (i + 1) * BKF;
            #pragma unroll
            for (int q = 0; q < 4; q++) bufA[q] = *(const float4*)(aBase + q * rstep + kt);
            #pragma unroll
            for (int p = 0; p < 8; p++) bufB[p] = *(const float4*)(bBase + p * rstep + kt);
        }

        __syncthreads();

        if (tid == 0) {
            FENCE_ASYNC();
            const uint32_t sb = tile_u32 + stage;
            const uint64_t dAh = mk_desc64(sb + A_HI_OFF);
            const uint64_t dAl = mk_desc64(sb + A_LO_OFF);
            const uint64_t dBh = mk_desc64(sb + B_HI_OFF);
            const uint64_t dBl = mk_desc64(sb + B_LO_OFF);
            const uint32_t en = (i != 0);
            // 4 independent chains: D(h, ks) at tmem + h*128 + ks*256
            #pragma unroll
            for (int ks = 0; ks < 2; ks++) {
                const uint64_t o  = 2 * ks;          // 16 bf16 = 32B = 2 units
                const uint32_t d0 = tmem + (uint32_t)ks * 256;        // half 0
                const uint32_t d1 = d0 + 128;                          // half 1
                mma_bf16_ss(d0, dAh + o, dBh + o,       en);
                mma_bf16_ss(d1, dAh + o, dBh + 512 + o, en);
                mma_bf16_ss(d0, dAh + o, dBl + o,       1);
                mma_bf16_ss(d1, dAh + o, dBl + 512 + o, 1);
                mma_bf16_ss(d0, dAl + o, dBh + o,       1);
                mma_bf16_ss(d1, dAl + o, dBh + 512 + o, 1);
            }
            if      (s == 0) TC_COMMIT(mbar_u32);
            else if (s == 1) TC_COMMIT(mbar_u32 + 8);
            else if (s == 2) TC_COMMIT(mbar_u32 + 16);
            else             TC_COMMIT(mbar_u32 + 24);
        }
    }

    // drain: final commit of each stage at current parity
    mbar_wait(mbar_u32,      ph0);
    mbar_wait(mbar_u32 + 8,  ph1);
    mbar_wait(mbar_u32 + 16, ph2);
    mbar_wait(mbar_u32 + 24, ph3);
    TC_FENCE_AFTER();

    // epilogue: warp handles half h = wid>>2, rows (wid&3)*32+lane.
    // C[m, h*128 + c] = D(h,0)[c] + D(h,1)[c]
    {
        const int m = blockRow + (wid & 3) * 32 + lane;
        const int h = wid >> 2;
        #pragma unroll
        for (int cb = 0; cb < 128; cb += 32) {
            uint32_t r0[32], r1[32];
            TC_LD_X32(r0, tmem + (uint32_t)h * 128 + cb);
            TC_LD_X32(r1, tmem + 256 + (uint32_t)h * 128 + cb);
            TC_WAIT_LD();
            float* cr = C + (size_t)m * E + h * 128 + cb;
            #pragma unroll
            for (int q = 0; q < 8; q++) {
                float4 v = make_float4(
                    __uint_as_float(r0[q * 4 + 0]) + __uint_as_float(r1[q * 4 + 0]),
                    __uint_as_float(r0[q * 4 + 1]) + __uint_as_float(r1[q * 4 + 1]),
                    __uint_as_float(r0[q * 4 + 2]) + __uint_as_float(r1[q * 4 + 2]),
                    __uint_as_float(r0[q * 4 + 3]) + __uint_as_float(r1[q * 4 + 3]));
                *(float4*)(cr + q * 4) = v;
            }
        }
        TC_FENCE_BEFORE();
    }
    __syncthreads();
    if (wid == 0) {
        TC_RELINQ();
        TC_DEALLOC(tmem, TMEM_NCOLS);
    }
#else
    // ==================== SIMT fp32 fallback ==================================
    __shared__ float As[BKF][128];
    __shared__ float Bs[BKF][128];

    const int tid = threadIdx.x;
    const int tx  = tid % 16;
    const int ty  = tid / 16;
    const int blockRow = blockIdx.x * BM;

    for (int half = 0; half < 2; half++) {
        const int blockCol = half * 128;
        const float* Ab = A + (size_t)blockRow * D;
        const float* Bb = W + (size_t)blockCol * D;

        float acc[8][8];
        #pragma unroll
        for (int i = 0; i < 8; i++)
            #pragma unroll
            for (int j = 0; j < 8; j++) acc[i][j] = 0.0f;

        const int lr = tid / 8;
        const int lc = tid % 8;

        for (int kt = 0; kt < D; kt += BKF) {
            __syncthreads();
            #pragma unroll
            for (int i = 0; i < 4; i++) {
                const int row = lr + i * 32;
                float4 va = *(const float4*)(Ab + (size_t)row * D + kt + lc * 4);
                As[lc * 4 + 0][row] = va.x;
                As[lc * 4 + 1][row] = va.y;
                As[lc * 4 + 2][row] = va.z;
                As[lc * 4 + 3][row] = va.w;
                float4 vb = *(const float4*)(Bb + (size_t)row * D + kt + lc * 4);
                Bs[lc * 4 + 0][row] = vb.x;
                Bs[lc * 4 + 1][row] = vb.y;
                Bs[lc * 4 + 2][row] = vb.z;
                Bs[lc * 4 + 3][row] = vb.w;
            }
            __syncthreads();

            #pragma unroll
            for (int k = 0; k < BKF; k++) {
                float a[8], b[8];
                *(float4*)&a[0] = *(const float4*)&As[k][ty * 8];
                *(float4*)&a[4] = *(const float4*)&As[k][ty * 8 + 4];
                *(float4*)&b[0] = *(const float4*)&Bs[k][tx * 8];
                *(float4*)&b[4] = *(const float4*)&Bs[k][tx * 8 + 4];
                #pragma unroll
                for (int i = 0; i < 8; i++)
                    #pragma unroll
                    for (int j = 0; j < 8; j++)
                        acc[i][j] = fmaf(a[i], b[j], acc[i][j]);
            }
        }

        #pragma unroll
        for (int i = 0; i < 8; i++) {
            const int row = blockRow + ty * 8 + i;
            float* Cr = C + (size_t)row * E + blockCol + tx * 8;
            *(float4*)(Cr + 0) = make_float4(acc[i][0], acc[i][1], acc[i][2], acc[i][3]);
            *(float4*)(Cr + 4) = make_float4(acc[i][4], acc[i][5], acc[i][6], acc[i][7]);
        }
        __syncthreads();
    }
#endif
}

// ---------------------------------------------------------------------------
// Router: TWO tokens per warp (interleaved for ILP); lane owns 8 experts of
// each token. Same per-token math/tie-break as the proven single-token warp.
// ---------------------------------------------------------------------------
__global__ __launch_bounds__(256)
void router_topk_kernel(const float* __restrict__ C,
                        const float* __restrict__ bias,
                        float* __restrict__ wout,
                        float* __restrict__ iout) {
    const int warp = threadIdx.x >> 5;
    const int lane = threadIdx.x & 31;
    const int t0   = blockIdx.x * 16 + warp * 2;   // tokens t0, t0+1

    const float4* bp = (const float4*)bias + lane * 2;
    float4 b0 = __ldg(bp), b1 = __ldg(bp + 1);
    float bl[8] = {b0.x, b0.y, b0.z, b0.w, b1.x, b1.y, b1.z, b1.w};

    float sc[2][8];
    #pragma unroll
    for (int tk = 0; tk < 2; tk++) {
        const float4* row = (const float4*)(C + (size_t)(t0 + tk) * 256) + lane * 2;
        float4 v0 = row[0], v1 = row[1];
        sc[tk][0] = v0.x; sc[tk][1] = v0.y; sc[tk][2] = v0.z; sc[tk][3] = v0.w;
        sc[tk][4] = v1.x; sc[tk][5] = v1.y; sc[tk][6] = v1.z; sc[tk][7] = v1.w;
    }

    // softmax (both tokens interleaved)
    float m[2];
    #pragma unroll
    for (int tk = 0; tk < 2; tk++) {
        m[tk] = sc[tk][0];
        #pragma unroll
        for (int j = 1; j < 8; j++) m[tk] = fmaxf(m[tk], sc[tk][j]);
    }
    #pragma unroll
    for (int off = 16; off > 0; off >>= 1) {
        m[0] = fmaxf(m[0], __shfl_xor_sync(0xffffffffu, m[0], off));
        m[1] = fmaxf(m[1], __shfl_xor_sync(0xffffffffu, m[1], off));
    }

    float su[2] = {0.0f, 0.0f};
    float ex[2][8];
    #pragma unroll
    for (int tk = 0; tk < 2; tk++)
        #pragma unroll
        for (int j = 0; j < 8; j++) { ex[tk][j] = __expf(sc[tk][j] - m[tk]); su[tk] += ex[tk][j]; }
    #pragma unroll
    for (int off = 16; off > 0; off >>= 1) {
        su[0] += __shfl_xor_sync(0xffffffffu, su[0], off);
        su[1] += __shfl_xor_sync(0xffffffffu, su[1], off);
    }

    float prob[2][8], choice[2][8];
    #pragma unroll
    for (int tk = 0; tk < 2; tk++) {
        const float inv = 1.0f / su[tk];
        #pragma unroll
        for (int j = 0; j < 8; j++) {
            prob[tk][j]   = ex[tk][j] * inv;
            choice[tk][j] = prob[tk][j] + bl[j];
        }
    }

    // cached local argmax per token (lowest j on ties via strict >)
    float v[2];
    int   li[2];
    #pragma unroll
    for (int tk = 0; tk < 2; tk++) {
        v[tk] = choice[tk][0]; li[tk] = 0;
        #pragma unroll
        for (int j = 1; j < 8; j++)
            if (choice[tk][j] > v[tk]) { v[tk] = choice[tk][j]; li[tk] = j; }
    }

    #pragma unroll
    for (int k = 0; k < TOP_K; k++) {
        float g0 = v[0], g1 = v[1];
        #pragma unroll
        for (int off = 16; off > 0; off >>= 1) {
            g0 = fmaxf(g0, __shfl_xor_sync(0xffffffffu, g0, off));
            g1 = fmaxf(g1, __shfl_xor_sync(0xffffffffu, g1, off));
        }
        unsigned mask0 = __ballot_sync(0xffffffffu, v[0] == g0);
        unsigned mask1 = __ballot_sync(0xffffffffu, v[1] == g1);
        const int src0 = __ffs(mask0) - 1;
        const int src1 = __ffs(mask1) - 1;

        if (lane == src0) {
            const int jj = li[0];
            float pw = 0.0f;
            #pragma unroll
            for (int j = 0; j < 8; j++)
                if (j == jj) { pw = prob[0][j]; choice[0][j] = -INFINITY; }
            wout[(size_t)t0 * TOP_K + k] = pw * ROUTED_SCALE;
            iout[(size_t)t0 * TOP_K + k] = (float)(lane * 8 + jj);
            v[0] = choice[0][0]; li[0] = 0;
            #pragma unroll
            for (int j = 1; j < 8; j++)
                if (choice[0][j] > v[0]) { v[0] = choice[0][j]; li[0] = j; }
        }
        if (lane == src1) {
            const int jj = li[1];
            float pw = 0.0f;
            #pragma unroll
            for (int j = 0; j < 8; j++)
                if (j == jj) { pw = prob[1][j]; choice[1][j] = -INFINITY; }
            wout[(size_t)(t0 + 1) * TOP_K + k] = pw * ROUTED_SCALE;
            iout[(size_t)(t0 + 1) * TOP_K + k] = (float)(lane * 8 + jj);
            v[1] = choice[1][0]; li[1] = 0;
            #pragma unroll
            for (int j = 1; j < 8; j++)
                if (choice[1][j] > v[1]) { v[1] = choice[1][j]; li[1] = j; }
        }
    }
}

// ----------------------------- launch ---------------------------------------
extern "C" void kernel_launch(void* const* d_in, const int* in_sizes, int n_in,
                              void* d_out, int out_size) {
    const float* H    = (const float*)d_in[0];  // [T, D]
    const float* W    = (const float*)d_in[1];  // [E, D]
    const float* bias = (const float*)d_in[2];  // [E]

    const int E = in_sizes[2];                  // 256
    const int D = in_sizes[1] / E;              // 4096
    const int T = in_sizes[0] / D;              // 16384

    float* out  = (float*)d_out;
    float* C    = out;                          // [T, E]
    float* wout = out + (size_t)T * E;          // [T, 8]
    float* iout = wout + (size_t)T * TOP_K;     // [T, 8]

    static int attr_set = 0;
    if (!attr_set) {
        cudaFuncSetAttribute(gemm_kernel,
                             cudaFuncAttributeMaxDynamicSharedMemorySize, DYN_SMEM);
        attr_set = 1;
    }

    gemm_kernel<<<T / BM, 256, DYN_SMEM>>>(H, W, C, D, E);
    router_topk_kernel<<<T / 16, 256>>>(C, bias, wout, iout);
}

// round 16
// speedup vs baseline: 1.7353x; 1.0626x over previous
#include <cuda_runtime.h>
#include <math.h>
#include <stdint.h>

// LongcatFlashTopkRouter: T=16384, D=4096, E=256
#define TOP_K 8
#define ROUTED_SCALE 1.5f

#if defined(__CUDA_ARCH__) && \
    (defined(__CUDA_ARCH_FEAT_SM103_ALL) || defined(__CUDA_ARCH_FEAT_SM100_ALL) || \
     defined(__CUDA_ARCH_FEAT_SM101_ALL))
#define HAS_TC 1
#else
#define HAS_TC 0
#endif

// ---------------------------------------------------------------------------
// GEMM: C[t,e] = dot(H[t,:], W[e,:]) via bf16x3 emulation on tcgen05.
// R9 champion core, byte-identical: 4 accumulator chains, NSTAGE=3.
// ---------------------------------------------------------------------------
#define BM 128
#define BN 256
#define BKF 32
#define STAGE_BYTES 49152
#define A_HI_OFF 0
#define A_LO_OFF 8192
#define B_HI_OFF 16384
#define B_LO_OFF 32768
#define NSTAGE 3
#define DYN_SMEM (NSTAGE * STAGE_BYTES + 1024)

// idesc kind::f16 bf16: F32(1)<<4 | BF16(1)<<7 | BF16(1)<<10 | (N=128/8)<<17 | (M=128/16)<<24
#define IDESC 0x8200490u
#define TMEM_NCOLS 512
// D accumulators: D(h, ks) at col h*128 + ks*256

#if HAS_TC
__device__ __forceinline__ uint32_t smem_u32(const void* p) {
    uint32_t a;
    asm("{ .reg .u64 t; cvta.to.shared.u64 t, %1; cvt.u32.u64 %0, t; }" : "=r"(a) : "l"(p));
    return a;
}

// d = { upper = bf16(hi), lower = bf16(lo) }
__device__ __forceinline__ uint32_t pack_bf16x2(float hi, float lo) {
    uint32_t d;
    asm("cvt.rn.bf16x2.f32 %0, %1, %2;" : "=r"(d) : "f"(hi), "f"(lo));
    return d;
}

#define SWZ64(o) ((o) ^ (((o) >> 3) & 0x30))

// SW64 K-major descriptor: layout=4, version=1, SBO=32 (512B/8rows), LBO=1
__device__ __forceinline__ uint64_t mk_desc64(uint32_t addr) {
    const uint64_t base =
        (uint64_t(4) << 61) | (uint64_t(1) << 46) | (uint64_t(32) << 32) | (uint64_t(1) << 16);
    return base | ((uint64_t)(addr >> 4) & 0x3FFF);
}

__device__ __forceinline__ void mma_bf16_ss(uint32_t d_tmem, uint64_t a_desc, uint64_t b_desc,
                                            uint32_t en) {
    uint32_t z = 0;
    asm volatile(
        "{\n\t.reg .pred p;\n\t"
        "setp.ne.u32 p, %5, 0;\n\t"
        "tcgen05.mma.cta_group::1.kind::f16 [%0], %1, %2, %3, {%4, %4, %4, %4}, p;\n\t}"
        :: "r"(d_tmem), "l"(a_desc), "l"(b_desc), "r"(IDESC), "r"(z), "r"(en)
        : "memory");
}

__device__ __forceinline__ void mbar_init(uint32_t mbar, uint32_t cnt) {
    asm volatile("mbarrier.init.shared.b64 [%0], %1;" :: "r"(mbar), "r"(cnt) : "memory");
}

__device__ __forceinline__ void mbar_wait(uint32_t mbar, uint32_t parity) {
    asm volatile(
        "{\n\t.reg .pred P;\n\t"
        "WL_%=:\n\t"
        "mbarrier.try_wait.parity.acquire.cta.shared::cta.b64 P, [%0], %1, 0x989680;\n\t"
        "@P bra.uni WD_%=;\n\t"
        "bra.uni WL_%=;\n\t"
        "WD_%=:\n\t}"
        :: "r"(mbar), "r"(parity) : "memory");
}

#define TC_ALLOC(dst_smem, n) \
    asm volatile("tcgen05.alloc.cta_group::1.sync.aligned.shared::cta.b32 [%0], %1;" \
                 :: "r"(dst_smem), "r"((uint32_t)(n)) : "memory")
#define TC_RELINQ() \
    asm volatile("tcgen05.relinquish_alloc_permit.cta_group::1.sync.aligned;")
#define TC_DEALLOC(tm, n) \
    asm volatile("tcgen05.dealloc.cta_group::1.sync.aligned.b32 %0, %1;" :: "r"(tm), "r"((uint32_t)(n)))
#define TC_COMMIT(mbar) \
    asm volatile("tcgen05.commit.cta_group::1.mbarrier::arrive::one.shared::cluster.b64 [%0];" \
                 :: "r"(mbar) : "memory")
#define TC_FENCE_AFTER()  asm volatile("tcgen05.fence::after_thread_sync;" ::: "memory")
#define TC_FENCE_BEFORE() asm volatile("tcgen05.fence::before_thread_sync;" ::: "memory")
#define FENCE_ASYNC() asm volatile("fence.proxy.async.shared::cta;" ::: "memory")
#define TC_WAIT_LD()  asm volatile("tcgen05.wait::ld.sync.aligned;" ::: "memory")

#define TC_LD_X32(r, addr) \
    asm volatile( \
        "tcgen05.ld.sync.aligned.32x32b.x32.b32 " \
        "{%0, %1, %2, %3, %4, %5, %6, %7, " \
        " %8, %9, %10, %11, %12, %13, %14, %15, " \
        " %16, %17, %18, %19, %20, %21, %22, %23, " \
        " %24, %25, %26, %27, %28, %29, %30, %31}, [%32];" \
        : "=r"((r)[0]),  "=r"((r)[1]),  "=r"((r)[2]),  "=r"((r)[3]), \
          "=r"((r)[4]),  "=r"((r)[5]),  "=r"((r)[6]),  "=r"((r)[7]), \
          "=r"((r)[8]),  "=r"((r)[9]),  "=r"((r)[10]), "=r"((r)[11]), \
          "=r"((r)[12]), "=r"((r)[13]), "=r"((r)[14]), "=r"((r)[15]), \
          "=r"((r)[16]), "=r"((r)[17]), "=r"((r)[18]), "=r"((r)[19]), \
          "=r"((r)[20]), "=r"((r)[21]), "=r"((r)[22]), "=r"((r)[23]), \
          "=r"((r)[24]), "=r"((r)[25]), "=r"((r)[26]), "=r"((r)[27]), \
          "=r"((r)[28]), "=r"((r)[29]), "=r"((r)[30]), "=r"((r)[31]) \
        : "r"(addr))
#endif  // HAS_TC

// warp-wide max: single redux on sm_100a-family, shuffle butterfly otherwise
__device__ __forceinline__ float warp_max_f32(float x) {
#if HAS_TC
    float r;
    asm("redux.sync.max.f32 %0, %1, 0xffffffff;" : "=f"(r) : "f"(x));
    return r;
#else
    #pragma unroll
    for (int off = 16; off > 0; off >>= 1)
        x = fmaxf(x, __shfl_xor_sync(0xffffffffu, x, off));
    return x;
#endif
}

extern __shared__ char g_dyn_smem[];

__global__ __launch_bounds__(256, 1)
void gemm_kernel(const float* __restrict__ A,   // [T, D]
                 const float* __restrict__ W,   // [E, D]
                 float* __restrict__ C,         // [T, E]
                 int D, int E) {
#if HAS_TC
    // ==================== tcgen05 bf16x3, 4 accumulator chains ===============
    __shared__ uint32_t s_tmem;
    __shared__ __align__(16) unsigned long long s_mbar[NSTAGE];

    const int tid  = threadIdx.x;
    const int wid  = tid >> 5;
    const int lane = tid & 31;

    uint32_t raw_u32  = smem_u32(g_dyn_smem);
    uint32_t tile_u32 = (raw_u32 + 1023u) & ~1023u;
    char*    tile_gen = g_dyn_smem + (tile_u32 - raw_u32);

    const uint32_t mbar_u32 = smem_u32(&s_mbar[0]);

    if (wid == 0) TC_ALLOC(smem_u32(&s_tmem), TMEM_NCOLS);
    if (tid == 0) {
        mbar_init(mbar_u32, 1);
        mbar_init(mbar_u32 + 8, 1);
        mbar_init(mbar_u32 + 16, 1);
    }
    __syncthreads();
    const uint32_t tmem = s_tmem;

    const int blockRow = blockIdx.x * BM;

    // producer mapping: group g = tid>>3 (0..31), f4 column tid&7 (0..7)
    const int grp = tid >> 3;
    const int c4  = tid & 7;

    const float* aBase = A + (size_t)(blockRow + grp) * D + c4 * 4;
    const float* bBase = W + (size_t)grp * D + c4 * 4;
    const size_t rstep = (size_t)32 * D;

    const int niter = D / BKF;   // 128
    int ph0 = 0, ph1 = 0, ph2 = 0;
    int s = 0;

    float4 bufA[4], bufB[8];
    #pragma unroll
    for (int q = 0; q < 4; q++) bufA[q] = *(const float4*)(aBase + q * rstep);
    #pragma unroll
    for (int p = 0; p < 8; p++) bufB[p] = *(const float4*)(bBase + p * rstep);

    const uint32_t rowOff = (uint32_t)(grp * 64 + c4 * 8);

    for (int i = 0; i < niter; i++) {
        const uint32_t stage = (uint32_t)s * STAGE_BYTES;

        if (i >= NSTAGE) {
            if      (s == 0) { mbar_wait(mbar_u32,      ph0); ph0 ^= 1; }
            else if (s == 1) { mbar_wait(mbar_u32 + 8,  ph1); ph1 ^= 1; }
            else             { mbar_wait(mbar_u32 + 16, ph2); ph2 ^= 1; }
        }

        // convert fp32 -> (hi, lo) bf16, swizzled STS
        #pragma unroll
        for (int q = 0; q < 4; q++) {
            const uint32_t off = SWZ64(rowOff + (uint32_t)q * 2048);
            float4 f = bufA[q];
            uint32_t h0 = pack_bf16x2(f.y, f.x);
            uint32_t h1 = pack_bf16x2(f.w, f.z);
            float a0 = __uint_as_float(h0 << 16);
            float a1 = __uint_as_float(h0 & 0xFFFF0000u);
            float a2 = __uint_as_float(h1 << 16);
            float a3 = __uint_as_float(h1 & 0xFFFF0000u);
            uint32_t l0 = pack_bf16x2(f.y - a1, f.x - a0);
            uint32_t l1 = pack_bf16x2(f.w - a3, f.z - a2);
            *(uint2*)(tile_gen + stage + A_HI_OFF + off) = make_uint2(h0, h1);
            *(uint2*)(tile_gen + stage + A_LO_OFF + off) = make_uint2(l0, l1);
        }
        #pragma unroll
        for (int p = 0; p < 8; p++) {
            const uint32_t off = SWZ64(rowOff + (uint32_t)p * 2048);
            float4 f = bufB[p];
            uint32_t h0 = pack_bf16x2(f.y, f.x);
            uint32_t h1 = pack_bf16x2(f.w, f.z);
            float a0 = __uint_as_float(h0 << 16);
            float a1 = __uint_as_float(h0 & 0xFFFF0000u);
            float a2 = __uint_as_float(h1 << 16);
            float a3 = __uint_as_float(h1 & 0xFFFF0000u);
            uint32_t l0 = pack_bf16x2(f.y - a1, f.x - a0);
            uint32_t l1 = pack_bf16x2(f.w - a3, f.z - a2);
            *(uint2*)(tile_gen + stage + B_HI_OFF + off) = make_uint2(h0, h1);
            *(uint2*)(tile_gen + stage + B_LO_OFF + off) = make_uint2(l0, l1);
        }

        if (i + 1 < niter) {
            const int kt = (i + 1) * BKF;
            #pragma unroll
            for (int q = 0; q < 4; q++) bufA[q] = *(const float4*)(aBase + q * rstep + kt);
            #pragma unroll
            for (int p = 0; p < 8; p++) bufB[p] = *(const float4*)(bBase + p * rstep + kt);
        }

        __syncthreads();

        if (tid == 0) {
            FENCE_ASYNC();
            const uint32_t sb = tile_u32 + stage;
            const uint64_t dAh = mk_desc64(sb + A_HI_OFF);
            const uint64_t dAl = mk_desc64(sb + A_LO_OFF);
            const uint64_t dBh = mk_desc64(sb + B_HI_OFF);
            const uint64_t dBl = mk_desc64(sb + B_LO_OFF);
            const uint32_t en = (i != 0);
            // 4 independent chains: D(h, ks) at tmem + h*128 + ks*256
            #pragma unroll
            for (int ks = 0; ks < 2; ks++) {
                const uint64_t o  = 2 * ks;          // 16 bf16 = 32B = 2 units
                const uint32_t d0 = tmem + (uint32_t)ks * 256;        // half 0
                const uint32_t d1 = d0 + 128;                          // half 1
                mma_bf16_ss(d0, dAh + o, dBh + o,       en);
                mma_bf16_ss(d1, dAh + o, dBh + 512 + o, en);
                mma_bf16_ss(d0, dAh + o, dBl + o,       1);
                mma_bf16_ss(d1, dAh + o, dBl + 512 + o, 1);
                mma_bf16_ss(d0, dAl + o, dBh + o,       1);
                mma_bf16_ss(d1, dAl + o, dBh + 512 + o, 1);
            }
            if      (s == 0) TC_COMMIT(mbar_u32);
            else if (s == 1) TC_COMMIT(mbar_u32 + 8);
            else             TC_COMMIT(mbar_u32 + 16);
        }

        s = (s == NSTAGE - 1) ? 0 : s + 1;
    }

    mbar_wait(mbar_u32,      ph0);
    mbar_wait(mbar_u32 + 8,  ph1);
    mbar_wait(mbar_u32 + 16, ph2);
    TC_FENCE_AFTER();

    // epilogue: warp handles half h = wid>>2, rows (wid&3)*32+lane.
    // C[m, h*128 + c] = D(h,0)[c] + D(h,1)[c]
    {
        const int m = blockRow + (wid & 3) * 32 + lane;
        const int h = wid >> 2;
        #pragma unroll
        for (int cb = 0; cb < 128; cb += 32) {
            uint32_t r0[32], r1[32];
            TC_LD_X32(r0, tmem + (uint32_t)h * 128 + cb);
            TC_LD_X32(r1, tmem + 256 + (uint32_t)h * 128 + cb);
            TC_WAIT_LD();
            float* cr = C + (size_t)m * E + h * 128 + cb;
            #pragma unroll
            for (int q = 0; q < 8; q++) {
                float4 v = make_float4(
                    __uint_as_float(r0[q * 4 + 0]) + __uint_as_float(r1[q * 4 + 0]),
                    __uint_as_float(r0[q * 4 + 1]) + __uint_as_float(r1[q * 4 + 1]),
                    __uint_as_float(r0[q * 4 + 2]) + __uint_as_float(r1[q * 4 + 2]),
                    __uint_as_float(r0[q * 4 + 3]) + __uint_as_float(r1[q * 4 + 3]));
                *(float4*)(cr + q * 4) = v;
            }
        }
        TC_FENCE_BEFORE();
    }
    __syncthreads();
    if (wid == 0) {
        TC_RELINQ();
        TC_DEALLOC(tmem, TMEM_NCOLS);
    }
#else
    // ==================== SIMT fp32 fallback ==================================
    __shared__ float As[BKF][128];
    __shared__ float Bs[BKF][128];

    const int tid = threadIdx.x;
    const int tx  = tid % 16;
    const int ty  = tid / 16;
    const int blockRow = blockIdx.x * BM;

    for (int half = 0; half < 2; half++) {
        const int blockCol = half * 128;
        const float* Ab = A + (size_t)blockRow * D;
        const float* Bb = W + (size_t)blockCol * D;

        float acc[8][8];
        #pragma unroll
        for (int i = 0; i < 8; i++)
            #pragma unroll
            for (int j = 0; j < 8; j++) acc[i][j] = 0.0f;

        const int lr = tid / 8;
        const int lc = tid % 8;

        for (int kt = 0; kt < D; kt += BKF) {
            __syncthreads();
            #pragma unroll
            for (int i = 0; i < 4; i++) {
                const int row = lr + i * 32;
                float4 va = *(const float4*)(Ab + (size_t)row * D + kt + lc * 4);
                As[lc * 4 + 0][row] = va.x;
                As[lc * 4 + 1][row] = va.y;
                As[lc * 4 + 2][row] = va.z;
                As[lc * 4 + 3][row] = va.w;
                float4 vb = *(const float4*)(Bb + (size_t)row * D + kt + lc * 4);
                Bs[lc * 4 + 0][row] = vb.x;
                Bs[lc * 4 + 1][row] = vb.y;
                Bs[lc * 4 + 2][row] = vb.z;
                Bs[lc * 4 + 3][row] = vb.w;
            }
            __syncthreads();

            #pragma unroll
            for (int k = 0; k < BKF; k++) {
                float a[8], b[8];
                *(float4*)&a[0] = *(const float4*)&As[k][ty * 8];
                *(float4*)&a[4] = *(const float4*)&As[k][ty * 8 + 4];
                *(float4*)&b[0] = *(const float4*)&Bs[k][tx * 8];
                *(float4*)&b[4] = *(const float4*)&Bs[k][tx * 8 + 4];
                #pragma unroll
                for (int i = 0; i < 8; i++)
                    #pragma unroll
                    for (int j = 0; j < 8; j++)
                        acc[i][j] = fmaf(a[i], b[j], acc[i][j]);
            }
        }

        #pragma unroll
        for (int i = 0; i < 8; i++) {
            const int row = blockRow + ty * 8 + i;
            float* Cr = C + (size_t)row * E + blockCol + tx * 8;
            *(float4*)(Cr + 0) = make_float4(acc[i][0], acc[i][1], acc[i][2], acc[i][3]);
            *(float4*)(Cr + 4) = make_float4(acc[i][4], acc[i][5], acc[i][6], acc[i][7]);
        }
        __syncthreads();
    }
#endif
}

// ---------------------------------------------------------------------------
// Router: warp per token; lane owns 8 experts. Max-reductions use
// redux.sync.max.f32 (single instruction) on sm_103a.
// ---------------------------------------------------------------------------
__global__ __launch_bounds__(256)
void router_topk_kernel(const float* __restrict__ C,
                        const float* __restrict__ bias,
                        float* __restrict__ wout,
                        float* __restrict__ iout) {
    const int t    = blockIdx.x * 8 + (threadIdx.x >> 5);
    const int lane = threadIdx.x & 31;

    const float4* row = (const float4*)(C + (size_t)t * 256) + lane * 2;
    float4 v0 = row[0], v1 = row[1];
    const float4* bp = (const float4*)bias + lane * 2;
    float4 b0 = __ldg(bp), b1 = __ldg(bp + 1);

    float sc[8] = {v0.x, v0.y, v0.z, v0.w, v1.x, v1.y, v1.z, v1.w};
    float bl[8] = {b0.x, b0.y, b0.z, b0.w, b1.x, b1.y, b1.z, b1.w};

    // softmax
    float m = sc[0];
    #pragma unroll
    for (int j = 1; j < 8; j++) m = fmaxf(m, sc[j]);
    m = warp_max_f32(m);

    float ex[8];
    float su = 0.0f;
    #pragma unroll
    for (int j = 0; j < 8; j++) { ex[j] = __expf(sc[j] - m); su += ex[j]; }
    #pragma unroll
    for (int off = 16; off > 0; off >>= 1)
        su += __shfl_xor_sync(0xffffffffu, su, off);
    const float inv = 1.0f / su;

    float prob[8], choice[8];
    #pragma unroll
    for (int j = 0; j < 8; j++) {
        prob[j]   = ex[j] * inv;
        choice[j] = prob[j] + bl[j];
    }

    // cached local argmax (lowest j on ties via strict >)
    float v = choice[0];
    int   li = 0;
    #pragma unroll
    for (int j = 1; j < 8; j++)
        if (choice[j] > v) { v = choice[j]; li = j; }

    #pragma unroll
    for (int k = 0; k < TOP_K; k++) {
        const float g = warp_max_f32(v);
        // lowest lane holding the max -> lowest global index
        unsigned mask = __ballot_sync(0xffffffffu, v == g);
        int src = __ffs(mask) - 1;
        if (lane == src) {
            float pw = 0.0f;
            #pragma unroll
            for (int j = 0; j < 8; j++)
                if (j == li) { pw = prob[j]; choice[j] = -INFINITY; }
            wout[(size_t)t * TOP_K + k] = pw * ROUTED_SCALE;
            iout[(size_t)t * TOP_K + k] = (float)(lane * 8 + li);
            v = choice[0]; li = 0;
            #pragma unroll
            for (int j = 1; j < 8; j++)
                if (choice[j] > v) { v = choice[j]; li = j; }
        }
    }
}

// ----------------------------- launch ---------------------------------------
extern "C" void kernel_launch(void* const* d_in, const int* in_sizes, int n_in,
                              void* d_out, int out_size) {
    const float* H    = (const float*)d_in[0];  // [T, D]
    const float* W    = (const float*)d_in[1];  // [E, D]
    const float* bias = (const float*)d_in[2];  // [E]

    const int E = in_sizes[2];                  // 256
    const int D = in_sizes[1] / E;              // 4096
    const int T = in_sizes[0] / D;              // 16384

    float* out  = (float*)d_out;
    float* C    = out;                          // [T, E]
    float* wout = out + (size_t)T * E;          // [T, 8]
    float* iout = wout + (size_t)T * TOP_K;     // [T, 8]

    static int attr_set = 0;
    if (!attr_set) {
        cudaFuncSetAttribute(gemm_kernel,
                             cudaFuncAttributeMaxDynamicSharedMemorySize, DYN_SMEM);
        attr_set = 1;
    }

    gemm_kernel<<<T / BM, 256, DYN_SMEM>>>(H, W, C, D, E);
    router_topk_kernel<<<T / 8, 256>>>(C, bias, wout, iout);
}